// round 4
// baseline (speedup 1.0000x reference)
#include <cuda_runtime.h>
#include <cuda_bf16.h>
#include <cstdint>
#include <math.h>

#define NPTS     524288
#define NGRIDS   64
#define GVOX     262144      /* 64^3 */
#define PTS_CTA  128
#define THREADS  256

#define FEAT_K   164
#define KPAD     176         /* 11 k-tiles of 16 */
#define S0       184         /* A0/B0 smem stride (bf16 elems), conflict-free */
#define S1       72          /* B1 smem stride */

__device__ float2   g_packed[NGRIDS * GVOX];      // channel-interleaved volumes
__device__ uint32_t g_feat[FEAT_K * NPTS];        // (lo<<16|hi) bf16 per (k,p)

// ---------------- smem layout for MLP kernel (bytes) ----------------
#define SM_A0H 0
#define SM_A0L (SM_A0H + PTS_CTA * S0 * 2)   /*  47104 */
#define SM_B0H (SM_A0L + PTS_CTA * S0 * 2)   /*  94208 */
#define SM_B0L (SM_B0H + 64 * S0 * 2)        /* 117760 */
#define SM_B1H (SM_B0L + 64 * S0 * 2)        /* 141312 */
#define SM_B1L (SM_B1H + 64 * S1 * 2)        /* 150528 */
#define SM_AUX (SM_B1L + 64 * S1 * 2)        /* 159744 */
#define SMEM_MLP (SM_AUX + 192 * 4)          /* 160512 */

// ---------------- helpers ----------------
__device__ __forceinline__ void mma16816(float* c, const uint32_t* a,
                                         uint32_t b0, uint32_t b1) {
    asm volatile(
        "mma.sync.aligned.m16n8k16.row.col.f32.bf16.bf16.f32 "
        "{%0,%1,%2,%3}, {%4,%5,%6,%7}, {%8,%9}, {%0,%1,%2,%3};"
        : "+f"(c[0]), "+f"(c[1]), "+f"(c[2]), "+f"(c[3])
        : "r"(a[0]), "r"(a[1]), "r"(a[2]), "r"(a[3]), "r"(b0), "r"(b1));
}
__device__ __forceinline__ void split2(float v0, float v1, uint32_t& hi,
                                       uint32_t& lo) {
    __nv_bfloat16 h0 = __float2bfloat16(v0), h1 = __float2bfloat16(v1);
    __nv_bfloat16 l0 = __float2bfloat16(v0 - __bfloat162float(h0));
    __nv_bfloat16 l1 = __float2bfloat16(v1 - __bfloat162float(h1));
    hi = ((uint32_t)__bfloat16_as_ushort(h1) << 16) | __bfloat16_as_ushort(h0);
    lo = ((uint32_t)__bfloat16_as_ushort(l1) << 16) | __bfloat16_as_ushort(l0);
}
__device__ __forceinline__ uint32_t pack_hl(float v) {
    __nv_bfloat16 h = __float2bfloat16(v);
    __nv_bfloat16 l = __float2bfloat16(v - __bfloat162float(h));
    return ((uint32_t)__bfloat16_as_ushort(l) << 16) | __bfloat16_as_ushort(h);
}
__device__ __forceinline__ float snake(float h) {
    float s = __sinf(h);
    return fmaf(0.5f, h, s * s);
}

// ---------------- repack: [g][c][v] f32 -> [g][v] float2 ----------------
__global__ void repack4(const float* __restrict__ fg) {
    int idx = blockIdx.x * blockDim.x + threadIdx.x;  // 0 .. 4194303
    int g = idx >> 16;
    int v4 = (idx & 65535) << 2;
    const float4 a = *(const float4*)(fg + (size_t)(2 * g) * GVOX + v4);
    const float4 b = *(const float4*)(fg + (size_t)(2 * g + 1) * GVOX + v4);
    float2* o = g_packed + ((size_t)g << 18) + v4;
    *(float4*)(o + 0) = make_float4(a.x, b.x, a.y, b.y);
    *(float4*)(o + 2) = make_float4(a.z, b.z, a.w, b.w);
}

// ---------------- kernel A: PE + grid gather -> g_feat ----------------
__global__ void __launch_bounds__(THREADS)
gather_kernel(const float* __restrict__ x,
              const float* __restrict__ gscale,
              const float* __restrict__ gtrans) {
    __shared__ float sc[192], tr[192];
    const int tid = threadIdx.x;
    for (int i = tid; i < 192; i += THREADS) {
        sc[i] = gscale[i];
        tr[i] = gtrans[i];
    }
    __syncthreads();

    const int p = tid & 127;
    const int half = tid >> 7;
    const int gpt = blockIdx.x * PTS_CTA + p;
    const float px = __ldg(&x[3 * gpt + 0]);
    const float py = __ldg(&x[3 * gpt + 1]);
    const float pz = __ldg(&x[3 * gpt + 2]);
    const float xyz[3] = {px, py, pz};

    // PE: half0 -> sin cols 0..17, half1 -> cos cols 18..35
    {
        const int cb = half ? 18 : 0;
#pragma unroll
        for (int l = 0; l < 6; l++) {
            float freq = 3.14159265358979323846f * (float)(1 << l);
#pragma unroll
            for (int d = 0; d < 3; d++) {
                float s, c;
                sincosf(xyz[d] * freq, &s, &c);
                g_feat[(size_t)(cb + l * 3 + d) * NPTS + gpt] =
                    pack_hl(half ? c : s);
            }
        }
    }

    // grids: half h handles grids [32h, 32h+32) -> cols 36+2g, 37+2g
#pragma unroll 1
    for (int gi = 0; gi < 32; gi++) {
        int g = half * 32 + gi;
        float sx = sc[3 * g + 0], sy = sc[3 * g + 1], sz = sc[3 * g + 2];
        float tx = tr[3 * g + 0], ty = tr[3 * g + 1], tz = tr[3 * g + 2];
        float ix = fmaf(fmaf(px, sx, tx), 31.5f, 31.5f);
        float iy = fmaf(fmaf(py, sy, ty), 31.5f, 31.5f);
        float iz = fmaf(fmaf(pz, sz, tz), 31.5f, 31.5f);
        float f0 = 0.f, f1 = 0.f;
        if (ix > -1.f && ix < 64.f && iy > -1.f && iy < 64.f && iz > -1.f &&
            iz < 64.f) {
            float fx = floorf(ix), fy = floorf(iy), fz = floorf(iz);
            int X0 = (int)fx, Y0 = (int)fy, Z0 = (int)fz;
            float wx1 = ix - fx, wy1 = iy - fy, wz1 = iz - fz;
            float wx0 = 1.f - wx1, wy0 = 1.f - wy1, wz0 = 1.f - wz1;
            if (X0 < 0)   wx0 = 0.f;
            if (X0 >= 63) wx1 = 0.f;
            if (Y0 < 0)   wy0 = 0.f;
            if (Y0 >= 63) wy1 = 0.f;
            if (Z0 < 0)   wz0 = 0.f;
            if (Z0 >= 63) wz1 = 0.f;
            int x0c = max(X0, 0), x1c = min(X0 + 1, 63);
            int y0c = max(Y0, 0), y1c = min(Y0 + 1, 63);
            int z0c = max(Z0, 0), z1c = min(Z0 + 1, 63);
            const float2* vol = g_packed + ((size_t)g << 18);
            int b00 = (z0c << 12) + (y0c << 6);
            int b01 = (z0c << 12) + (y1c << 6);
            int b10 = (z1c << 12) + (y0c << 6);
            int b11 = (z1c << 12) + (y1c << 6);
            float2 v000 = __ldg(&vol[b00 + x0c]);
            float2 v001 = __ldg(&vol[b00 + x1c]);
            float2 v010 = __ldg(&vol[b01 + x0c]);
            float2 v011 = __ldg(&vol[b01 + x1c]);
            float2 v100 = __ldg(&vol[b10 + x0c]);
            float2 v101 = __ldg(&vol[b10 + x1c]);
            float2 v110 = __ldg(&vol[b11 + x0c]);
            float2 v111 = __ldg(&vol[b11 + x1c]);
            float w00 = wz0 * wy0, w01 = wz0 * wy1;
            float w10 = wz1 * wy0, w11 = wz1 * wy1;
            float c000 = w00 * wx0, c001 = w00 * wx1;
            float c010 = w01 * wx0, c011 = w01 * wx1;
            float c100 = w10 * wx0, c101 = w10 * wx1;
            float c110 = w11 * wx0, c111 = w11 * wx1;
            f0 = c000 * v000.x;
            f1 = c000 * v000.y;
            f0 = fmaf(c001, v001.x, f0); f1 = fmaf(c001, v001.y, f1);
            f0 = fmaf(c010, v010.x, f0); f1 = fmaf(c010, v010.y, f1);
            f0 = fmaf(c011, v011.x, f0); f1 = fmaf(c011, v011.y, f1);
            f0 = fmaf(c100, v100.x, f0); f1 = fmaf(c100, v100.y, f1);
            f0 = fmaf(c101, v101.x, f0); f1 = fmaf(c101, v101.y, f1);
            f0 = fmaf(c110, v110.x, f0); f1 = fmaf(c110, v110.y, f1);
            f0 = fmaf(c111, v111.x, f0); f1 = fmaf(c111, v111.y, f1);
        }
        int col = 36 + 2 * g;
        g_feat[(size_t)col * NPTS + gpt] = pack_hl(f0);
        g_feat[(size_t)(col + 1) * NPTS + gpt] = pack_hl(f1);
    }
}

// ---------------- kernel B: HMMA MLP ----------------
__global__ void __launch_bounds__(THREADS, 1)
mlp_kernel(const float* __restrict__ W0,
           const float* __restrict__ b0,
           const float* __restrict__ W1,
           const float* __restrict__ b1,
           const float* __restrict__ W2,
           const float* __restrict__ b2,
           float* __restrict__ out) {
    extern __shared__ char smem[];
    float* auxf = (float*)(smem + SM_AUX);
    const int tid = threadIdx.x;

    // ---- stage B0 hi/lo [n][k], k padded to 176 ----
    for (int i = tid; i < 64 * 88; i += THREADS) {
        int n = i & 63, k = (i >> 6) * 2;
        float v0 = (k < FEAT_K) ? W0[k * 64 + n] : 0.f;
        float v1 = (k + 1 < FEAT_K) ? W0[(k + 1) * 64 + n] : 0.f;
        uint32_t hi, lo;
        split2(v0, v1, hi, lo);
        *(uint32_t*)(smem + SM_B0H + (n * S0 + k) * 2) = hi;
        *(uint32_t*)(smem + SM_B0L + (n * S0 + k) * 2) = lo;
    }
    // ---- stage B1 hi/lo [n][j] ----
    for (int i = tid; i < 64 * 32; i += THREADS) {
        int n = i & 63, j = (i >> 6) * 2;
        uint32_t hi, lo;
        split2(W1[j * 64 + n], W1[(j + 1) * 64 + n], hi, lo);
        *(uint32_t*)(smem + SM_B1H + (n * S1 + j) * 2) = hi;
        *(uint32_t*)(smem + SM_B1L + (n * S1 + j) * 2) = lo;
    }
    // ---- stage A0 from global feature buffer (coalesced) ----
    {
        const int pbase = blockIdx.x * PTS_CTA;
#pragma unroll 1
        for (int i = tid; i < 82 * PTS_CTA; i += THREADS) {
            int p = i & 127, kp = i >> 7;
            int k = kp * 2;
            uint32_t w0 = g_feat[(size_t)k * NPTS + pbase + p];
            uint32_t w1 = g_feat[(size_t)(k + 1) * NPTS + pbase + p];
            *(uint32_t*)(smem + SM_A0H + (p * S0 + k) * 2) =
                __byte_perm(w0, w1, 0x5410);
            *(uint32_t*)(smem + SM_A0L + (p * S0 + k) * 2) =
                __byte_perm(w0, w1, 0x7632);
        }
        // zero pad cols 164..175
        for (int i = tid; i < PTS_CTA * 6; i += THREADS) {
            int p = i / 6, k = 164 + (i % 6) * 2;
            *(uint32_t*)(smem + SM_A0H + (p * S0 + k) * 2) = 0u;
            *(uint32_t*)(smem + SM_A0L + (p * S0 + k) * 2) = 0u;
        }
    }
    for (int i = tid; i < 64; i += THREADS) {
        auxf[i] = b0[i];
        auxf[64 + i] = b1[i];
        auxf[128 + i] = W2[i];
    }
    __syncthreads();

    // ---- MMA phase: warp w owns points [16w,16w+16), all 64 outs ----
    const int lane = tid & 31;
    const int gid = lane >> 2;
    const int tid4 = lane & 3;
    const int p0 = (tid >> 5) * 16;
    const char* A0H = smem + SM_A0H;
    const char* A0L = smem + SM_A0L;
    const char* B0H = smem + SM_B0H;
    const char* B0L = smem + SM_B0L;
    const char* B1H = smem + SM_B1H;
    const char* B1L = smem + SM_B1L;

    float acc0[8][4];
#pragma unroll
    for (int nt = 0; nt < 8; nt++)
#pragma unroll
        for (int j = 0; j < 4; j++) acc0[nt][j] = 0.f;

    const int rA = (p0 + gid) * S0;
    const int rA8 = (p0 + gid + 8) * S0;
#pragma unroll 1
    for (int kt = 0; kt < 11; kt++) {
        const int k0 = kt * 16 + tid4 * 2;
        uint32_t aH[4], aL[4];
        aH[0] = *(const uint32_t*)(A0H + (rA + k0) * 2);
        aH[1] = *(const uint32_t*)(A0H + (rA8 + k0) * 2);
        aH[2] = *(const uint32_t*)(A0H + (rA + k0 + 8) * 2);
        aH[3] = *(const uint32_t*)(A0H + (rA8 + k0 + 8) * 2);
        aL[0] = *(const uint32_t*)(A0L + (rA + k0) * 2);
        aL[1] = *(const uint32_t*)(A0L + (rA8 + k0) * 2);
        aL[2] = *(const uint32_t*)(A0L + (rA + k0 + 8) * 2);
        aL[3] = *(const uint32_t*)(A0L + (rA8 + k0 + 8) * 2);
#pragma unroll
        for (int nt = 0; nt < 8; nt++) {
            const int rB = (nt * 8 + gid) * S0;
            uint32_t bh0 = *(const uint32_t*)(B0H + (rB + k0) * 2);
            uint32_t bh1 = *(const uint32_t*)(B0H + (rB + k0 + 8) * 2);
            uint32_t bl0 = *(const uint32_t*)(B0L + (rB + k0) * 2);
            uint32_t bl1 = *(const uint32_t*)(B0L + (rB + k0 + 8) * 2);
            mma16816(acc0[nt], aH, bh0, bh1);
            mma16816(acc0[nt], aL, bh0, bh1);
            mma16816(acc0[nt], aH, bl0, bl1);
        }
    }

    // ---- epilogue 0: bias + snake -> layer1 A fragments (registers) ----
    uint32_t a1H[4][4], a1L[4][4];
#pragma unroll
    for (int nt = 0; nt < 8; nt++) {
        int cb = nt * 8 + tid4 * 2;
        float ba = auxf[cb], bb = auxf[cb + 1];
        float v0 = snake(acc0[nt][0] + ba);
        float v1 = snake(acc0[nt][1] + bb);
        float v2 = snake(acc0[nt][2] + ba);
        float v3 = snake(acc0[nt][3] + bb);
        int kt1 = nt >> 1, h = (nt & 1) * 2;
        split2(v0, v1, a1H[kt1][h + 0], a1L[kt1][h + 0]);
        split2(v2, v3, a1H[kt1][h + 1], a1L[kt1][h + 1]);
    }

    // ---- layer 1 MMA ----
    float acc1[8][4];
#pragma unroll
    for (int nt = 0; nt < 8; nt++)
#pragma unroll
        for (int j = 0; j < 4; j++) acc1[nt][j] = 0.f;
#pragma unroll
    for (int kt = 0; kt < 4; kt++) {
        const int k0 = kt * 16 + tid4 * 2;
#pragma unroll
        for (int nt = 0; nt < 8; nt++) {
            const int rB = (nt * 8 + gid) * S1;
            uint32_t bh0 = *(const uint32_t*)(B1H + (rB + k0) * 2);
            uint32_t bh1 = *(const uint32_t*)(B1H + (rB + k0 + 8) * 2);
            uint32_t bl0 = *(const uint32_t*)(B1L + (rB + k0) * 2);
            uint32_t bl1 = *(const uint32_t*)(B1L + (rB + k0 + 8) * 2);
            mma16816(acc1[nt], a1H[kt], bh0, bh1);
            mma16816(acc1[nt], a1L[kt], bh0, bh1);
            mma16816(acc1[nt], a1H[kt], bl0, bl1);
        }
    }

    // ---- epilogue 1: bias + snake + dot(W2) + quad reduce ----
    float pr0 = 0.f, pr8 = 0.f;
#pragma unroll
    for (int nt = 0; nt < 8; nt++) {
        int cb = nt * 8 + tid4 * 2;
        float b1a = auxf[64 + cb], b1b = auxf[64 + cb + 1];
        float w2a = auxf[128 + cb], w2b = auxf[128 + cb + 1];
        pr0 = fmaf(snake(acc1[nt][0] + b1a), w2a, pr0);
        pr0 = fmaf(snake(acc1[nt][1] + b1b), w2b, pr0);
        pr8 = fmaf(snake(acc1[nt][2] + b1a), w2a, pr8);
        pr8 = fmaf(snake(acc1[nt][3] + b1b), w2b, pr8);
    }
    pr0 += __shfl_xor_sync(0xffffffffu, pr0, 1);
    pr0 += __shfl_xor_sync(0xffffffffu, pr0, 2);
    pr8 += __shfl_xor_sync(0xffffffffu, pr8, 1);
    pr8 += __shfl_xor_sync(0xffffffffu, pr8, 2);
    if (tid4 == 0) {
        float b2v = __ldg(b2);
        int base = blockIdx.x * PTS_CTA + p0;
        out[base + gid] = pr0 + b2v;
        out[base + gid + 8] = pr8 + b2v;
    }
}

extern "C" void kernel_launch(void* const* d_in, const int* in_sizes, int n_in,
                              void* d_out, int out_size) {
    const float* x      = (const float*)d_in[0];
    const float* gsc    = (const float*)d_in[1];
    const float* gtr    = (const float*)d_in[2];
    const float* fgrids = (const float*)d_in[3];
    const float* W0     = (const float*)d_in[4];
    const float* b0     = (const float*)d_in[5];
    const float* W1     = (const float*)d_in[6];
    const float* b1     = (const float*)d_in[7];
    const float* W2     = (const float*)d_in[8];
    const float* b2     = (const float*)d_in[9];
    float* out          = (float*)d_out;

    cudaFuncSetAttribute(mlp_kernel, cudaFuncAttributeMaxDynamicSharedMemorySize,
                         SMEM_MLP);

    repack4<<<(NGRIDS * GVOX / 4) / 256, 256>>>(fgrids);
    gather_kernel<<<NPTS / PTS_CTA, THREADS>>>(x, gsc, gtr);
    mlp_kernel<<<NPTS / PTS_CTA, THREADS, SMEM_MLP>>>(W0, b0, W1, b1, W2, b2,
                                                      out);
}

// round 5
// speedup vs baseline: 1.9067x; 1.9067x over previous
#include <cuda_runtime.h>
#include <cuda_bf16.h>
#include <cstdint>
#include <math.h>

#define NPTS    524288
#define NGRIDS  64
#define GVOX    262144      /* 64^3 */
#define PE_L    6

// Channel-interleaved feature volumes: [g][z][y][x] -> {c0, c1}
__device__ float2 g_packed[NGRIDS * GVOX];   // 128 MB static scratch

// ---------------- packed f32x2 helpers ----------------
__device__ __forceinline__ void fma2(unsigned long long& d,
                                     unsigned long long a,
                                     unsigned long long b) {
    asm("fma.rn.f32x2 %0, %1, %2, %0;" : "+l"(d) : "l"(a), "l"(b));
}
__device__ __forceinline__ unsigned long long bcast2(float f) {
    unsigned long long r;
    asm("mov.b64 %0, {%1, %2};" : "=l"(r) : "f"(f), "f"(f));
    return r;
}
__device__ __forceinline__ float2 unpack2(unsigned long long v) {
    float2 f;
    asm("mov.b64 {%0, %1}, %2;" : "=f"(f.x), "=f"(f.y) : "l"(v));
    return f;
}
__device__ __forceinline__ unsigned long long pack2(float a, float b) {
    unsigned long long r;
    asm("mov.b64 %0, {%1, %2};" : "=l"(r) : "f"(a), "f"(b));
    return r;
}

// acc[0..31] += f * row[0..63]  (row: 16B-aligned smem, 64 contiguous floats)
__device__ __forceinline__ void accum_row(unsigned long long* acc,
                                          const float* row, float f) {
    unsigned long long ff = bcast2(f);
    const ulonglong2* r2 = reinterpret_cast<const ulonglong2*>(row);
#pragma unroll
    for (int i = 0; i < 16; i++) {
        ulonglong2 w = r2[i];
        fma2(acc[2 * i], ff, w.x);
        fma2(acc[2 * i + 1], ff, w.y);
    }
}

// ---------------- repack: [g][c][v] f32 -> [g][v] float2 ----------------
__global__ void repack4(const float* __restrict__ fg) {
    int idx = blockIdx.x * blockDim.x + threadIdx.x;  // 0 .. 4194303
    int g = idx >> 16;
    int v4 = (idx & 65535) << 2;
    const float4 a = *(const float4*)(fg + (size_t)(2 * g) * GVOX + v4);
    const float4 b = *(const float4*)(fg + (size_t)(2 * g + 1) * GVOX + v4);
    float2* o = g_packed + ((size_t)g << 18) + v4;
    *(float4*)(o + 0) = make_float4(a.x, b.x, a.y, b.y);
    *(float4*)(o + 2) = make_float4(a.z, b.z, a.w, b.w);
}

// ---------------- smem layout (floats) ----------------
#define OFF_PE   0                         // 36*64  = 2304 (PE rows, broadcast)
#define OFF_W0G  (OFF_PE + 36 * 64)        // 64*132 = 8448 (per-grid 128f + pad)
#define OFF_W1T  (OFF_W0G + 64 * 132)      // 64*64  = 4096 (transposed [k][j])
#define OFF_W2   (OFF_W1T + 64 * 64)       // 64
#define OFF_B1   (OFF_W2 + 64)             // 64
#define OFF_B0   (OFF_B1 + 64)             // 64
#define OFF_GP   (OFF_B0 + 64)             // 64*8 = 512 (packed params)
#define SMEM_FLOATS (OFF_GP + 512)
#define SMEM_BYTES  (SMEM_FLOATS * 4)      // 62 KB -> 2 CTAs/SM

__global__ void __launch_bounds__(256, 2)
amrsrn_main(const float* __restrict__ x,
            const float* __restrict__ gscale,
            const float* __restrict__ gtrans,
            const float* __restrict__ W0,
            const float* __restrict__ b0,
            const float* __restrict__ W1,
            const float* __restrict__ b1,
            const float* __restrict__ W2,
            const float* __restrict__ b2,
            float* __restrict__ out) {
    extern __shared__ float sm[];
    int tid = threadIdx.x;

    // ---- stage weights ----
    for (int i = tid; i < 36 * 64; i += 256) sm[OFF_PE + i] = W0[i];
    // per-grid record: [g][0..63] = W0 row 36+2g, [g][64..127] = row 37+2g
    for (int i = tid; i < 64 * 128; i += 256) {
        int g = i >> 7, j = i & 127;
        int row = 36 + 2 * g + (j >> 6);
        sm[OFF_W0G + g * 132 + j] = W0[row * 64 + (j & 63)];
    }
    for (int i = tid; i < 64 * 64; i += 256) {   // transpose W1 -> [k][j]
        int j = i >> 6, k = i & 63;
        sm[OFF_W1T + k * 64 + j] = W1[i];
    }
    for (int i = tid; i < 64; i += 256) {
        sm[OFF_W2 + i] = W2[i];
        sm[OFF_B1 + i] = b1[i];
        sm[OFF_B0 + i] = b0[i];
    }
    for (int i = tid; i < 64; i += 256) {        // packed grid params
        sm[OFF_GP + i * 8 + 0] = gscale[3 * i + 0];
        sm[OFF_GP + i * 8 + 1] = gscale[3 * i + 1];
        sm[OFF_GP + i * 8 + 2] = gscale[3 * i + 2];
        sm[OFF_GP + i * 8 + 3] = gtrans[3 * i + 0];
        sm[OFF_GP + i * 8 + 4] = gtrans[3 * i + 1];
        sm[OFF_GP + i * 8 + 5] = gtrans[3 * i + 2];
        sm[OFF_GP + i * 8 + 6] = 0.f;
        sm[OFF_GP + i * 8 + 7] = 0.f;
    }
    __syncthreads();

    int pt = blockIdx.x * 256 + tid;
    float px = __ldg(&x[3 * pt + 0]);
    float py = __ldg(&x[3 * pt + 1]);
    float pz = __ldg(&x[3 * pt + 2]);
    float xyz[3] = {px, py, pz};
    const float4* gp4 = (const float4*)&sm[OFF_GP];

    // ---- h0 accumulators (32 packed f32x2), init = b0 ----
    unsigned long long acc[32];
    const unsigned long long* pb0 =
        reinterpret_cast<const unsigned long long*>(&sm[OFF_B0]);
#pragma unroll
    for (int i = 0; i < 32; i++) acc[i] = pb0[i];

    // ---- positional encoding into h0 (broadcast rows) ----
#pragma unroll 1
    for (int l = 0; l < PE_L; l++) {
        float freq = 3.14159265358979323846f * (float)(1 << l);
#pragma unroll
        for (int d = 0; d < 3; d++) {
            float s, c;
            sincosf(xyz[d] * freq, &s, &c);
            accum_row(acc, &sm[OFF_PE + (l * 3 + d) * 64], s);
            accum_row(acc, &sm[OFF_PE + (18 + l * 3 + d) * 64], c);
        }
    }

    // ---- pass 1: validity mask (pure ALU) ----
    unsigned long long mask = 0ull;
#pragma unroll 1
    for (int g = 0; g < 64; g++) {
        float4 p1 = gp4[g * 2];
        float4 p2 = gp4[g * 2 + 1];
        float ix = fmaf(fmaf(px, p1.x, p1.w), 31.5f, 31.5f);
        float iy = fmaf(fmaf(py, p1.y, p2.x), 31.5f, 31.5f);
        float iz = fmaf(fmaf(pz, p1.z, p2.y), 31.5f, 31.5f);
        if (ix > -1.f && ix < 64.f && iy > -1.f && iy < 64.f && iz > -1.f &&
            iz < 64.f)
            mask |= 1ull << g;
    }

    // ---- pass 2: compacted sparse accumulation ----
    while (__ballot_sync(0xffffffffu, mask != 0ull)) {
        bool active = (mask != 0ull);
        if (active) {
            int g = __ffsll((long long)mask) - 1;
            mask &= mask - 1;
            float4 p1 = gp4[g * 2];
            float4 p2 = gp4[g * 2 + 1];
            float ix = fmaf(fmaf(px, p1.x, p1.w), 31.5f, 31.5f);
            float iy = fmaf(fmaf(py, p1.y, p2.x), 31.5f, 31.5f);
            float iz = fmaf(fmaf(pz, p1.z, p2.y), 31.5f, 31.5f);
            float fx = floorf(ix), fy = floorf(iy), fz = floorf(iz);
            int X0 = (int)fx, Y0 = (int)fy, Z0 = (int)fz;
            float wx1 = ix - fx, wy1 = iy - fy, wz1 = iz - fz;
            float wx0 = 1.f - wx1, wy0 = 1.f - wy1, wz0 = 1.f - wz1;
            if (X0 < 0)   wx0 = 0.f;
            if (X0 >= 63) wx1 = 0.f;
            if (Y0 < 0)   wy0 = 0.f;
            if (Y0 >= 63) wy1 = 0.f;
            if (Z0 < 0)   wz0 = 0.f;
            if (Z0 >= 63) wz1 = 0.f;
            int x0c = max(X0, 0), x1c = min(X0 + 1, 63);
            int y0c = max(Y0, 0), y1c = min(Y0 + 1, 63);
            int z0c = max(Z0, 0), z1c = min(Z0 + 1, 63);

            const float2* vol = g_packed + ((size_t)g << 18);
            int b00 = (z0c << 12) + (y0c << 6);
            int b01 = (z0c << 12) + (y1c << 6);
            int b10 = (z1c << 12) + (y0c << 6);
            int b11 = (z1c << 12) + (y1c << 6);
            float2 v000 = __ldg(&vol[b00 + x0c]);
            float2 v001 = __ldg(&vol[b00 + x1c]);
            float2 v010 = __ldg(&vol[b01 + x0c]);
            float2 v011 = __ldg(&vol[b01 + x1c]);
            float2 v100 = __ldg(&vol[b10 + x0c]);
            float2 v101 = __ldg(&vol[b10 + x1c]);
            float2 v110 = __ldg(&vol[b11 + x0c]);
            float2 v111 = __ldg(&vol[b11 + x1c]);

            float w00 = wz0 * wy0, w01 = wz0 * wy1;
            float w10 = wz1 * wy0, w11 = wz1 * wy1;
            float c000 = w00 * wx0, c001 = w00 * wx1;
            float c010 = w01 * wx0, c011 = w01 * wx1;
            float c100 = w10 * wx0, c101 = w10 * wx1;
            float c110 = w11 * wx0, c111 = w11 * wx1;

            float f0 = c000 * v000.x, f1 = c000 * v000.y;
            f0 = fmaf(c001, v001.x, f0); f1 = fmaf(c001, v001.y, f1);
            f0 = fmaf(c010, v010.x, f0); f1 = fmaf(c010, v010.y, f1);
            f0 = fmaf(c011, v011.x, f0); f1 = fmaf(c011, v011.y, f1);
            f0 = fmaf(c100, v100.x, f0); f1 = fmaf(c100, v100.y, f1);
            f0 = fmaf(c101, v101.x, f0); f1 = fmaf(c101, v101.y, f1);
            f0 = fmaf(c110, v110.x, f0); f1 = fmaf(c110, v110.y, f1);
            f0 = fmaf(c111, v111.x, f0); f1 = fmaf(c111, v111.y, f1);

            const float* wrow = &sm[OFF_W0G + g * 132];
            accum_row(acc, wrow, f0);
            accum_row(acc, wrow + 64, f1);
        }
    }

    // ---- snake activation on h0 (in place, stays packed) ----
#pragma unroll
    for (int i = 0; i < 32; i++) {
        float2 h = unpack2(acc[i]);
        float s0 = __sinf(h.x), s1 = __sinf(h.y);
        acc[i] = pack2(fmaf(0.5f, h.x, s0 * s0), fmaf(0.5f, h.y, s1 * s1));
    }

    // ---- layer1 (broadcast rows of W1T) + snake + layer2 ----
    float outv = 0.f;
#pragma unroll 1
    for (int k = 0; k < 64; k++) {
        const ulonglong2* r2 =
            reinterpret_cast<const ulonglong2*>(&sm[OFF_W1T + k * 64]);
        unsigned long long a0 = 0ull, a1 = 0ull, a2 = 0ull, a3 = 0ull;
#pragma unroll
        for (int j = 0; j < 8; j++) {
            ulonglong2 wA = r2[2 * j];
            ulonglong2 wB = r2[2 * j + 1];
            fma2(a0, acc[4 * j + 0], wA.x);
            fma2(a1, acc[4 * j + 1], wA.y);
            fma2(a2, acc[4 * j + 2], wB.x);
            fma2(a3, acc[4 * j + 3], wB.y);
        }
        float2 fa = unpack2(a0), fb = unpack2(a1), fc = unpack2(a2),
               fd = unpack2(a3);
        float h = ((fa.x + fa.y) + (fb.x + fb.y)) +
                  ((fc.x + fc.y) + (fd.x + fd.y)) + sm[OFF_B1 + k];
        float s = __sinf(h);
        outv = fmaf(fmaf(0.5f, h, s * s), sm[OFF_W2 + k], outv);
    }

    out[pt] = outv + __ldg(b2);
}

extern "C" void kernel_launch(void* const* d_in, const int* in_sizes, int n_in,
                              void* d_out, int out_size) {
    const float* x      = (const float*)d_in[0];
    const float* gsc    = (const float*)d_in[1];
    const float* gtr    = (const float*)d_in[2];
    const float* fgrids = (const float*)d_in[3];
    const float* W0     = (const float*)d_in[4];
    const float* b0     = (const float*)d_in[5];
    const float* W1     = (const float*)d_in[6];
    const float* b1     = (const float*)d_in[7];
    const float* W2     = (const float*)d_in[8];
    const float* b2     = (const float*)d_in[9];
    float* out          = (float*)d_out;

    cudaFuncSetAttribute(amrsrn_main,
                         cudaFuncAttributeMaxDynamicSharedMemorySize,
                         SMEM_BYTES);

    repack4<<<(NGRIDS * GVOX / 4) / 256, 256>>>(fgrids);
    amrsrn_main<<<NPTS / 256, 256, SMEM_BYTES>>>(x, gsc, gtr, W0, b0, W1, b1,
                                                 W2, b2, out);
}